// round 4
// baseline (speedup 1.0000x reference)
#include <cuda_runtime.h>
#include <cstdint>
#include <math.h>

#define BATCH  4096
#define TT     12
#define NROWS  (BATCH*TT)       // 49152
#define DIN    1536
#define DSC    234
#define KTOT   1770
#define KTILES 56               // ceil(1770/32) -> padded to 1792
#define DM     64
#define DSS    8
#define NC     234
#define NSITES 20

// ---------------- scratch (no allocations allowed) ----------------
__device__ float g_h[NROWS*DM];       // post-(GEMM1,LN,gelu,+meta,+pos)  == residual
__device__ float g_y[NROWS*2*DM];     // concat(h_f, h_b)
__device__ float g_meta[BATCH*DM];

// ---------------- helpers ----------------
__device__ __forceinline__ float tf32r(float x){
    float r; asm("cvt.rna.tf32.f32 %0, %1;" : "=f"(r) : "f"(x)); return r;
}
__device__ __forceinline__ void mma8(float* c, const uint32_t* a, const uint32_t* b){
    asm volatile("mma.sync.aligned.m16n8k8.row.col.f32.tf32.tf32.f32 "
        "{%0,%1,%2,%3},{%4,%5,%6,%7},{%8,%9},{%0,%1,%2,%3};\n"
        : "+f"(c[0]),"+f"(c[1]),"+f"(c[2]),"+f"(c[3])
        : "r"(a[0]),"r"(a[1]),"r"(a[2]),"r"(a[3]),"r"(b[0]),"r"(b[1]));
}
__device__ __forceinline__ float warp_sum(float v){
    #pragma unroll
    for(int o=16;o;o>>=1) v += __shfl_xor_sync(0xffffffffu, v, o);
    return v;
}
__device__ __forceinline__ float gelu_exact(float x){
    return 0.5f*x*(1.0f + erff(x*0.70710678118654752f));
}
__device__ __forceinline__ float softplusf(float x){
    return (x > 20.0f) ? x : log1pf(expf(x));
}

// ================= kernel 0: meta embedding GEMM =================
__global__ void k_meta(const int* __restrict__ site_ids, const int* __restrict__ hours,
                       const float* __restrict__ site_emb, const float* __restrict__ hour_emb,
                       const float* __restrict__ W_meta, const float* __restrict__ b_meta){
    int idx = blockIdx.x*blockDim.x + threadIdx.x;   // B*64 total
    int b = idx >> 6, d = idx & 63;
    int s = site_ids[b]; s = min(max(s,0), NSITES-1);
    int hh = hours[b];   hh = min(max(hh,0), 23);
    float acc = b_meta[d];
    #pragma unroll
    for(int j=0;j<8;j++){
        acc += site_emb[s*8+j]*W_meta[j*64+d];
        acc += hour_emb[hh*8+j]*W_meta[(8+j)*64+d];
    }
    g_meta[idx] = acc;
}

// ================= kernel 1: big GEMM (tf32) + LN + gelu + meta/pos =================
__device__ __forceinline__ void k1_loadA(const float* __restrict__ emb, const float* __restrict__ scores,
                                         long row, int lkh, int ki, float* ra){
    int kbase = ki*32 + lkh*16;
    if(ki < 48){
        const float4* p = reinterpret_cast<const float4*>(emb + row*DIN + kbase);
        #pragma unroll
        for(int q=0;q<4;q++){
            float4 v = p[q];
            ra[4*q+0]=v.x; ra[4*q+1]=v.y; ra[4*q+2]=v.z; ra[4*q+3]=v.w;
        }
    } else {
        int sb = kbase - DIN;
        const float* p = scores + row*DSC;
        #pragma unroll
        for(int j=0;j<16;j++){
            int s = sb + j;
            ra[j] = (s < DSC) ? p[s] : 0.0f;
        }
    }
}
__device__ __forceinline__ void k1_loadW(const float* __restrict__ W, int wkr, int wn8, int ki, float* rw){
    int kg = ki*32 + wkr;
    if(kg < KTOT){
        const float4* p = reinterpret_cast<const float4*>(W + (long)kg*DM + wn8);
        float4 v0 = p[0], v1 = p[1];
        rw[0]=v0.x;rw[1]=v0.y;rw[2]=v0.z;rw[3]=v0.w;
        rw[4]=v1.x;rw[5]=v1.y;rw[6]=v1.z;rw[7]=v1.w;
    } else {
        #pragma unroll
        for(int j=0;j<8;j++) rw[j]=0.0f;
    }
}
__device__ __forceinline__ void k1_mma(const float* __restrict__ As, const float* __restrict__ Ws,
                                       int wm, int wn, int gid, int tig, float acc[2][4][4]){
    #pragma unroll
    for(int kk=0;kk<32;kk+=8){
        uint32_t af[2][4];
        #pragma unroll
        for(int mt=0;mt<2;mt++){
            int m = wm*32 + mt*16 + gid;
            af[mt][0] = __float_as_uint(As[(kk+tig  )*136 + m    ]);
            af[mt][1] = __float_as_uint(As[(kk+tig  )*136 + m + 8]);
            af[mt][2] = __float_as_uint(As[(kk+tig+4)*136 + m    ]);
            af[mt][3] = __float_as_uint(As[(kk+tig+4)*136 + m + 8]);
        }
        #pragma unroll
        for(int nt=0;nt<4;nt++){
            int n = wn*32 + nt*8 + gid;
            uint32_t bf[2];
            bf[0] = __float_as_uint(Ws[(kk+tig  )*72 + n]);
            bf[1] = __float_as_uint(Ws[(kk+tig+4)*72 + n]);
            #pragma unroll
            for(int mt=0;mt<2;mt++) mma8(acc[mt][nt], af[mt], bf);
        }
    }
}

__global__ void __launch_bounds__(256)
k1(const float* __restrict__ emb, const float* __restrict__ scores,
   const float* __restrict__ W_in, const float* __restrict__ b_in,
   const float* __restrict__ lg, const float* __restrict__ lb,
   const float* __restrict__ pos_enc){
    extern __shared__ float sm[];
    float* As = sm;            // 2 * 32 * 136 = 8704 floats
    float* Ws = sm + 8704;     // 2 * 32 * 72  = 4608 floats
    float* Ht = sm;            // epilogue reuse: 128 * 72

    const int tid = threadIdx.x, lane = tid & 31, warp = tid >> 5;
    const int gid = lane >> 2, tig = lane & 3;
    const int wm = warp & 3, wn = warp >> 2;
    const int lm = tid & 127, lkh = tid >> 7;
    const int wkr = tid >> 3, wn8 = (tid & 7) * 8;
    const long m0 = (long)blockIdx.x * 128;
    const long arow = m0 + lm;

    float acc[2][4][4];
    #pragma unroll
    for(int i=0;i<2;i++)
        #pragma unroll
        for(int j=0;j<4;j++)
            #pragma unroll
            for(int q=0;q<4;q++) acc[i][j][q]=0.0f;

    float ra[16], rw[8];
    k1_loadA(emb, scores, arow, lkh, 0, ra);
    k1_loadW(W_in, wkr, wn8, 0, rw);
    {
        #pragma unroll
        for(int j=0;j<16;j++) As[(lkh*16+j)*136 + lm] = tf32r(ra[j]);
        #pragma unroll
        for(int j=0;j<8;j++)  Ws[wkr*72 + wn8 + j]   = tf32r(rw[j]);
    }
    __syncthreads();

    int buf = 0;
    for(int ki=0; ki<KTILES; ki++){
        if(ki+1 < KTILES){
            k1_loadA(emb, scores, arow, lkh, ki+1, ra);
            k1_loadW(W_in, wkr, wn8, ki+1, rw);
        }
        k1_mma(As + buf*4352, Ws + buf*2304, wm, wn, gid, tig, acc);
        if(ki+1 < KTILES){
            float* dA = As + (buf^1)*4352;
            float* dW = Ws + (buf^1)*2304;
            #pragma unroll
            for(int j=0;j<16;j++) dA[(lkh*16+j)*136 + lm] = tf32r(ra[j]);
            #pragma unroll
            for(int j=0;j<8;j++)  dW[wkr*72 + wn8 + j]   = tf32r(rw[j]);
        }
        __syncthreads();
        buf ^= 1;
    }

    // scatter accumulators into smem tile
    #pragma unroll
    for(int mt=0;mt<2;mt++)
        #pragma unroll
        for(int nt=0;nt<4;nt++){
            int r = wm*32 + mt*16 + gid;
            int c = wn*32 + nt*8 + 2*tig;
            Ht[ r   *72 + c    ] = acc[mt][nt][0];
            Ht[ r   *72 + c + 1] = acc[mt][nt][1];
            Ht[(r+8)*72 + c    ] = acc[mt][nt][2];
            Ht[(r+8)*72 + c + 1] = acc[mt][nt][3];
        }
    __syncthreads();

    // per-row: +b_in, LN, gelu, +meta, +pos -> g_h
    const float bin0 = b_in[lane], bin1 = b_in[lane+32];
    const float gg0 = lg[lane], gg1 = lg[lane+32];
    const float ee0 = lb[lane], ee1 = lb[lane+32];
    #pragma unroll 1
    for(int i=0;i<16;i++){
        int r = warp*16 + i;
        float v0 = Ht[r*72 + lane   ] + bin0;
        float v1 = Ht[r*72 + lane+32] + bin1;
        float mu = warp_sum(v0+v1) * (1.0f/64.0f);
        float d0 = v0-mu, d1 = v1-mu;
        float var = warp_sum(d0*d0 + d1*d1) * (1.0f/64.0f);
        float rs = rsqrtf(var + 1e-5f);
        float y0 = gelu_exact(d0*rs*gg0 + ee0);
        float y1 = gelu_exact(d1*rs*gg1 + ee1);
        long grow = m0 + r;
        int bb = (int)(grow / TT), tt2 = (int)(grow % TT);
        y0 += g_meta[bb*64 + lane   ] + pos_enc[tt2*64 + lane   ];
        y1 += g_meta[bb*64 + lane+32] + pos_enc[tt2*64 + lane+32];
        g_h[grow*64 + lane   ] = y0;
        g_h[grow*64 + lane+32] = y1;
    }
}

// ================= kernel 2: proj GEMM + bidirectional SSM scan =================
__global__ void __launch_bounds__(128)
k2(const float* __restrict__ Wp_f, const float* __restrict__ bp_f,
   const float* __restrict__ A_log_f, const float* __restrict__ D_f,
   const float* __restrict__ Wp_b, const float* __restrict__ bp_b,
   const float* __restrict__ A_log_b, const float* __restrict__ D_b){
    extern __shared__ float sm[];
    float* hs  = sm;            // 12*64   = 768
    float* Wpc = sm + 768;      // 64*160  = 10240
    float* prj = sm + 11008;    // 12*160  = 1920
    float* bpc = sm + 12928;    // 160

    const int tid = threadIdx.x;
    const int b = blockIdx.x;

    const float* hrow = g_h + (long)b*TT*DM;
    for(int i=tid;i<TT*DM;i+=128) hs[i] = hrow[i];
    for(int i=tid;i<64*160;i+=128){
        int d = i/160, j = i%160;
        Wpc[i] = (j<80) ? Wp_f[d*80+j] : Wp_b[d*80+(j-80)];
    }
    // FIX (R3): previous version did `if(tid<160)` with blockDim==128,
    // leaving bpc[128..159] (backward delta-tail/Bc/Cc biases) uninitialized.
    for(int i=tid;i<160;i+=128) bpc[i] = (i<80) ? bp_f[i] : bp_b[i-80];
    __syncthreads();

    // proj[t][j] = hs[t] . Wpc[:,j] + bpc[j]
    for(int i=tid;i<TT*160;i+=128){
        int t = i/160, j = i%160;
        float a = bpc[j];
        const float* hr = hs + t*64;
        #pragma unroll 8
        for(int d=0;d<64;d++) a += hr[d]*Wpc[d*160+j];
        prj[i] = a;
    }
    __syncthreads();

    // scan: warps 0-1 forward, warps 2-3 backward (no divergence)
    const int dir = tid >> 6;     // 0 fwd, 1 bwd
    const int d = tid & 63;
    const float* Alog = dir ? A_log_b : A_log_f;
    float Arow[DSS];
    #pragma unroll
    for(int n=0;n<DSS;n++) Arow[n] = -expf(Alog[d*DSS+n]);
    const float Dd = dir ? D_b[d] : D_f[d];
    float h[DSS];
    #pragma unroll
    for(int n=0;n<DSS;n++) h[n]=0.0f;
    float* yout = g_y + (long)b*TT*128 + dir*64 + d;
    const int joff = dir ? 80 : 0;

    for(int s=0;s<TT;s++){
        int t = dir ? (TT-1-s) : s;
        const float* p = prj + t*160 + joff;
        float delta = softplusf(p[d]);
        float x = hs[t*64 + d];
        float dx = delta * x;
        float y = 0.0f;
        #pragma unroll
        for(int n=0;n<DSS;n++){
            float dA = expf(delta * Arow[n]);
            h[n] = dA*h[n] + dx*p[64+n];     // Bc
            y += h[n]*p[72+n];               // Cc
        }
        yout[t*128] = y + x*Dd;
    }
}

// ================= kernel 3: merge GEMM + residual + LN + out GEMM =================
__global__ void __launch_bounds__(256)
k3(const float* __restrict__ W_merge, const float* __restrict__ b_merge,
   const float* __restrict__ lgm, const float* __restrict__ lbm,
   const float* __restrict__ W_out, const float* __restrict__ b_out,
   float* __restrict__ out){
    extern __shared__ float sm[];
    float* Wm   = sm;             // 128*64 = 8192
    float* Wo   = sm + 8192;      // 64*240 = 15360 (padded)
    float* bm   = sm + 23552;     // 64
    float* lgs  = sm + 23616;     // 64
    float* lbs  = sm + 23680;     // 64
    float* bo   = sm + 23744;     // 240
    float* ybuf = sm + 23984;     // 8*128
    float* h2   = sm + 25008;     // 8*64   -> total 25520 floats

    const int tid = threadIdx.x, lane = tid & 31, warp = tid >> 5;
    for(int i=tid;i<128*64;i+=256) Wm[i] = W_merge[i];
    for(int i=tid;i<64*NC;i+=256){ int d=i/NC, o=i%NC; Wo[d*240+o] = W_out[i]; }
    if(tid<64){ bm[tid]=b_merge[tid]; lgs[tid]=lgm[tid]; lbs[tid]=lbm[tid]; }
    for(int i=tid;i<NC;i+=256) bo[i] = b_out[i];
    __syncthreads();

    float* yb = ybuf + warp*128;
    float* hb = h2   + warp*64;
    const long m0 = (long)blockIdx.x*128;

    for(int i=0;i<16;i++){
        long r = m0 + warp*16 + i;
        const float* yr = g_y + r*128;
        #pragma unroll
        for(int q=0;q<4;q++) yb[lane + 32*q] = yr[lane + 32*q];
        __syncwarp();

        float a0 = bm[lane], a1 = bm[lane+32];
        #pragma unroll 8
        for(int k=0;k<128;k++){
            float yv = yb[k];
            a0 += yv*Wm[k*64 + lane];
            a1 += yv*Wm[k*64 + lane+32];
        }
        a0 += g_h[r*64 + lane];
        a1 += g_h[r*64 + lane+32];

        float mu = warp_sum(a0+a1) * (1.0f/64.0f);
        float d0 = a0-mu, d1 = a1-mu;
        float var = warp_sum(d0*d0 + d1*d1) * (1.0f/64.0f);
        float rs = rsqrtf(var + 1e-5f);
        hb[lane   ] = d0*rs*lgs[lane   ] + lbs[lane   ];
        hb[lane+32] = d1*rs*lgs[lane+32] + lbs[lane+32];
        __syncwarp();

        float* orow = out + r*NC;
        #pragma unroll
        for(int q=0;q<8;q++){
            int o = lane + 32*q;
            if(o < NC){
                float a = bo[o];
                #pragma unroll 8
                for(int d2=0;d2<64;d2++) a += hb[d2]*Wo[d2*240 + o];
                orow[o] = a;
            }
        }
        __syncwarp();   // before yb/hb reuse next iteration
    }
}

// ================= launch =================
extern "C" void kernel_launch(void* const* d_in, const int* in_sizes, int n_in,
                              void* d_out, int out_size){
    const float* emb      = (const float*)d_in[0];
    const float* scores   = (const float*)d_in[1];
    const int*   site_ids = (const int*)  d_in[2];
    const int*   hours    = (const int*)  d_in[3];
    const float* W_in     = (const float*)d_in[4];
    const float* b_in     = (const float*)d_in[5];
    const float* ln_in_g  = (const float*)d_in[6];
    const float* ln_in_b  = (const float*)d_in[7];
    const float* site_emb = (const float*)d_in[8];
    const float* hour_emb = (const float*)d_in[9];
    const float* W_meta   = (const float*)d_in[10];
    const float* b_meta   = (const float*)d_in[11];
    const float* pos_enc  = (const float*)d_in[12];
    const float* A_log_f  = (const float*)d_in[13];
    const float* Wp_f     = (const float*)d_in[14];
    const float* bp_f     = (const float*)d_in[15];
    const float* D_f      = (const float*)d_in[16];
    const float* A_log_b  = (const float*)d_in[17];
    const float* Wp_b     = (const float*)d_in[18];
    const float* bp_b     = (const float*)d_in[19];
    const float* D_b      = (const float*)d_in[20];
    const float* W_merge  = (const float*)d_in[21];
    const float* b_merge  = (const float*)d_in[22];
    const float* ln_g     = (const float*)d_in[23];
    const float* ln_b     = (const float*)d_in[24];
    const float* W_out    = (const float*)d_in[25];
    const float* b_out    = (const float*)d_in[26];
    float* out = (float*)d_out;

    cudaFuncSetAttribute(k1, cudaFuncAttributeMaxDynamicSharedMemorySize, 53248);
    cudaFuncSetAttribute(k2, cudaFuncAttributeMaxDynamicSharedMemorySize, 52352);
    cudaFuncSetAttribute(k3, cudaFuncAttributeMaxDynamicSharedMemorySize, 102080);

    k_meta<<<(BATCH*DM)/256, 256>>>(site_ids, hours, site_emb, hour_emb, W_meta, b_meta);
    k1<<<NROWS/128, 256, 53248>>>(emb, scores, W_in, b_in, ln_in_g, ln_in_b, pos_enc);
    k2<<<BATCH, 128, 52352>>>(Wp_f, bp_f, A_log_f, D_f, Wp_b, bp_b, A_log_b, D_b);
    k3<<<NROWS/128, 256, 102080>>>(W_merge, b_merge, ln_g, ln_b, W_out, b_out, out);
}

// round 6
// speedup vs baseline: 1.7329x; 1.7329x over previous
#include <cuda_runtime.h>
#include <cstdint>
#include <math.h>

#define BATCH  4096
#define TT     12
#define NROWS  (BATCH*TT)       // 49152
#define DIN    1536
#define DSC    234
#define KTOT   1770
#define KTILES 56
#define DM     64
#define DSS    8
#define NC     234
#define NSITES 20

// ---------------- scratch (no allocations allowed) ----------------
__device__ float g_h[NROWS*DM];        // residual after stage 1
__device__ float g_y[NROWS*2*DM];      // concat(h_f, h_b)
__device__ float g_meta[BATCH*DM];
__device__ float g_prj[NROWS*160];     // proj (fwd 0:80 | bwd 80:160), bias included

// ---------------- helpers ----------------
__device__ __forceinline__ float tf32r(float x){
    float r; asm("cvt.rna.tf32.f32 %0, %1;" : "=f"(r) : "f"(x)); return r;
}
__device__ __forceinline__ void mma8(float* c, const uint32_t* a, const uint32_t* b){
    asm volatile("mma.sync.aligned.m16n8k8.row.col.f32.tf32.tf32.f32 "
        "{%0,%1,%2,%3},{%4,%5,%6,%7},{%8,%9},{%0,%1,%2,%3};\n"
        : "+f"(c[0]),"+f"(c[1]),"+f"(c[2]),"+f"(c[3])
        : "r"(a[0]),"r"(a[1]),"r"(a[2]),"r"(a[3]),"r"(b[0]),"r"(b[1]));
}
__device__ __forceinline__ float warp_sum(float v){
    #pragma unroll
    for(int o=16;o;o>>=1) v += __shfl_xor_sync(0xffffffffu, v, o);
    return v;
}
__device__ __forceinline__ float gelu_exact(float x){
    return 0.5f*x*(1.0f + erff(x*0.70710678118654752f));
}
__device__ __forceinline__ float softplusf(float x){
    return (x > 20.0f) ? x : log1pf(expf(x));
}

// ================= kernel 0: meta embedding GEMM =================
__global__ void k_meta(const int* __restrict__ site_ids, const int* __restrict__ hours,
                       const float* __restrict__ site_emb, const float* __restrict__ hour_emb,
                       const float* __restrict__ W_meta, const float* __restrict__ b_meta){
    int idx = blockIdx.x*blockDim.x + threadIdx.x;
    int b = idx >> 6, d = idx & 63;
    int s = site_ids[b]; s = min(max(s,0), NSITES-1);
    int hh = hours[b];   hh = min(max(hh,0), 23);
    float acc = b_meta[d];
    #pragma unroll
    for(int j=0;j<8;j++){
        acc += site_emb[s*8+j]*W_meta[j*64+d];
        acc += hour_emb[hh*8+j]*W_meta[(8+j)*64+d];
    }
    g_meta[idx] = acc;
}

// ================= kernel 1: big GEMM (tf32) + LN + gelu + meta/pos =================
__device__ __forceinline__ void k1_loadA(const float* __restrict__ emb, const float* __restrict__ scores,
                                         long row, int lkh, int ki, float* ra){
    int kbase = ki*32 + lkh*16;
    if(ki < 48){
        const float4* p = reinterpret_cast<const float4*>(emb + row*DIN + kbase);
        #pragma unroll
        for(int q=0;q<4;q++){
            float4 v = p[q];
            ra[4*q+0]=v.x; ra[4*q+1]=v.y; ra[4*q+2]=v.z; ra[4*q+3]=v.w;
        }
    } else {
        int sb = kbase - DIN;
        const float* p = scores + row*DSC;
        #pragma unroll
        for(int j=0;j<16;j++){
            int s = sb + j;
            ra[j] = (s < DSC) ? p[s] : 0.0f;
        }
    }
}
__device__ __forceinline__ void k1_loadW(const float* __restrict__ W, int wkr, int wn8, int ki, float* rw){
    int kg = ki*32 + wkr;
    if(kg < KTOT){
        const float4* p = reinterpret_cast<const float4*>(W + (long)kg*DM + wn8);
        float4 v0 = p[0], v1 = p[1];
        rw[0]=v0.x;rw[1]=v0.y;rw[2]=v0.z;rw[3]=v0.w;
        rw[4]=v1.x;rw[5]=v1.y;rw[6]=v1.z;rw[7]=v1.w;
    } else {
        #pragma unroll
        for(int j=0;j<8;j++) rw[j]=0.0f;
    }
}
__device__ __forceinline__ void k1_mma(const float* __restrict__ As, const float* __restrict__ Ws,
                                       int wm, int wn, int gid, int tig, float acc[2][4][4]){
    #pragma unroll
    for(int kk=0;kk<32;kk+=8){
        uint32_t af[2][4];
        #pragma unroll
        for(int mt=0;mt<2;mt++){
            int m = wm*32 + mt*16 + gid;
            af[mt][0] = __float_as_uint(As[(kk+tig  )*136 + m    ]);
            af[mt][1] = __float_as_uint(As[(kk+tig  )*136 + m + 8]);
            af[mt][2] = __float_as_uint(As[(kk+tig+4)*136 + m    ]);
            af[mt][3] = __float_as_uint(As[(kk+tig+4)*136 + m + 8]);
        }
        #pragma unroll
        for(int nt=0;nt<4;nt++){
            int n = wn*32 + nt*8 + gid;
            uint32_t bf[2];
            bf[0] = __float_as_uint(Ws[(kk+tig  )*72 + n]);
            bf[1] = __float_as_uint(Ws[(kk+tig+4)*72 + n]);
            #pragma unroll
            for(int mt=0;mt<2;mt++) mma8(acc[mt][nt], af[mt], bf);
        }
    }
}

__global__ void __launch_bounds__(256)
k1(const float* __restrict__ emb, const float* __restrict__ scores,
   const float* __restrict__ W_in, const float* __restrict__ b_in,
   const float* __restrict__ lg, const float* __restrict__ lb,
   const float* __restrict__ pos_enc){
    extern __shared__ float sm[];
    float* As = sm;            // 2 * 32 * 136
    float* Ws = sm + 8704;     // 2 * 32 * 72
    float* Ht = sm;            // epilogue reuse

    const int tid = threadIdx.x, lane = tid & 31, warp = tid >> 5;
    const int gid = lane >> 2, tig = lane & 3;
    const int wm = warp & 3, wn = warp >> 2;
    const int lm = tid & 127, lkh = tid >> 7;
    const int wkr = tid >> 3, wn8 = (tid & 7) * 8;
    const long m0 = (long)blockIdx.x * 128;
    const long arow = m0 + lm;

    float acc[2][4][4];
    #pragma unroll
    for(int i=0;i<2;i++)
        #pragma unroll
        for(int j=0;j<4;j++)
            #pragma unroll
            for(int q=0;q<4;q++) acc[i][j][q]=0.0f;

    float ra[16], rw[8];
    k1_loadA(emb, scores, arow, lkh, 0, ra);
    k1_loadW(W_in, wkr, wn8, 0, rw);
    {
        #pragma unroll
        for(int j=0;j<16;j++) As[(lkh*16+j)*136 + lm] = tf32r(ra[j]);
        #pragma unroll
        for(int j=0;j<8;j++)  Ws[wkr*72 + wn8 + j]   = tf32r(rw[j]);
    }
    __syncthreads();

    int buf = 0;
    for(int ki=0; ki<KTILES; ki++){
        if(ki+1 < KTILES){
            k1_loadA(emb, scores, arow, lkh, ki+1, ra);
            k1_loadW(W_in, wkr, wn8, ki+1, rw);
        }
        k1_mma(As + buf*4352, Ws + buf*2304, wm, wn, gid, tig, acc);
        if(ki+1 < KTILES){
            float* dA = As + (buf^1)*4352;
            float* dW = Ws + (buf^1)*2304;
            #pragma unroll
            for(int j=0;j<16;j++) dA[(lkh*16+j)*136 + lm] = tf32r(ra[j]);
            #pragma unroll
            for(int j=0;j<8;j++)  dW[wkr*72 + wn8 + j]   = tf32r(rw[j]);
        }
        __syncthreads();
        buf ^= 1;
    }

    #pragma unroll
    for(int mt=0;mt<2;mt++)
        #pragma unroll
        for(int nt=0;nt<4;nt++){
            int r = wm*32 + mt*16 + gid;
            int c = wn*32 + nt*8 + 2*tig;
            Ht[ r   *72 + c    ] = acc[mt][nt][0];
            Ht[ r   *72 + c + 1] = acc[mt][nt][1];
            Ht[(r+8)*72 + c    ] = acc[mt][nt][2];
            Ht[(r+8)*72 + c + 1] = acc[mt][nt][3];
        }
    __syncthreads();

    const float bin0 = b_in[lane], bin1 = b_in[lane+32];
    const float gg0 = lg[lane], gg1 = lg[lane+32];
    const float ee0 = lb[lane], ee1 = lb[lane+32];
    #pragma unroll 1
    for(int i=0;i<16;i++){
        int r = warp*16 + i;
        float v0 = Ht[r*72 + lane   ] + bin0;
        float v1 = Ht[r*72 + lane+32] + bin1;
        float mu = warp_sum(v0+v1) * (1.0f/64.0f);
        float d0 = v0-mu, d1 = v1-mu;
        float var = warp_sum(d0*d0 + d1*d1) * (1.0f/64.0f);
        float rs = rsqrtf(var + 1e-5f);
        float y0 = gelu_exact(d0*rs*gg0 + ee0);
        float y1 = gelu_exact(d1*rs*gg1 + ee1);
        long grow = m0 + r;
        int bb = (int)(grow / TT), tt2 = (int)(grow % TT);
        y0 += g_meta[bb*64 + lane   ] + pos_enc[tt2*64 + lane   ];
        y1 += g_meta[bb*64 + lane+32] + pos_enc[tt2*64 + lane+32];
        g_h[grow*64 + lane   ] = y0;
        g_h[grow*64 + lane+32] = y1;
    }
}

// ================= kernel 2a: proj GEMM (tf32 TC): g_prj = g_h @ [Wp_f|Wp_b] + bias ====
// M=49152 (128/CTA), N=160, K=64
__global__ void __launch_bounds__(256)
k2a(const float* __restrict__ Wp_f, const float* __restrict__ bp_f,
    const float* __restrict__ Wp_b, const float* __restrict__ bp_b){
    extern __shared__ float sm[];
    float* Hs  = sm;            // 128*68  = 8704
    float* Wps = sm + 8704;     // 64*168  = 10752
    float* bps = sm + 19456;    // 160
    float* Pt  = sm + 19616;    // 128*172 = 22016  -> total 41632 fl

    const int tid = threadIdx.x, lane = tid & 31, warp = tid >> 5;
    const int gid = lane >> 2, tig = lane & 3;
    const int wm = warp & 3, wn = warp >> 2;       // 4m x 2n, warp tile 32x80
    const long m0 = (long)blockIdx.x * 128;

    // load H tile [128x64] row-major, stride 68, tf32
    {
        int n4 = tid & 15, r0 = tid >> 4;
        #pragma unroll
        for(int r=r0; r<128; r+=16){
            float4 v = *reinterpret_cast<const float4*>(g_h + (m0+r)*64 + n4*4);
            float4 w; w.x=tf32r(v.x); w.y=tf32r(v.y); w.z=tf32r(v.z); w.w=tf32r(v.w);
            *reinterpret_cast<float4*>(Hs + r*68 + n4*4) = w;
        }
    }
    // load Wp combined [64x160] stride 168
    for(int i=tid;i<64*160;i+=256){
        int k = i/160, j = i%160;
        Wps[k*168+j] = tf32r((j<80) ? Wp_f[k*80+j] : Wp_b[k*80+(j-80)]);
    }
    for(int i=tid;i<160;i+=256) bps[i] = (i<80) ? bp_f[i] : bp_b[i-80];
    __syncthreads();

    float acc[2][10][4];
    #pragma unroll
    for(int a=0;a<2;a++)
        #pragma unroll
        for(int b=0;b<10;b++)
            #pragma unroll
            for(int q=0;q<4;q++) acc[a][b][q]=0.0f;

    #pragma unroll
    for(int kk=0;kk<64;kk+=8){
        uint32_t af[2][4];
        #pragma unroll
        for(int mt=0;mt<2;mt++){
            int m = wm*32 + mt*16 + gid;
            af[mt][0] = __float_as_uint(Hs[ m   *68 + kk+tig  ]);
            af[mt][1] = __float_as_uint(Hs[(m+8)*68 + kk+tig  ]);
            af[mt][2] = __float_as_uint(Hs[ m   *68 + kk+tig+4]);
            af[mt][3] = __float_as_uint(Hs[(m+8)*68 + kk+tig+4]);
        }
        #pragma unroll
        for(int nt=0;nt<10;nt++){
            int n = wn*80 + nt*8 + gid;
            uint32_t bf[2];
            bf[0] = __float_as_uint(Wps[(kk+tig  )*168 + n]);
            bf[1] = __float_as_uint(Wps[(kk+tig+4)*168 + n]);
            #pragma unroll
            for(int mt=0;mt<2;mt++) mma8(acc[mt][nt], af[mt], bf);
        }
    }

    // scatter + bias into Pt
    #pragma unroll
    for(int mt=0;mt<2;mt++)
        #pragma unroll
        for(int nt=0;nt<10;nt++){
            int r = wm*32 + mt*16 + gid;
            int c = wn*80 + nt*8 + 2*tig;
            float b0 = bps[c], b1 = bps[c+1];
            Pt[ r   *172 + c    ] = acc[mt][nt][0] + b0;
            Pt[ r   *172 + c + 1] = acc[mt][nt][1] + b1;
            Pt[(r+8)*172 + c    ] = acc[mt][nt][2] + b0;
            Pt[(r+8)*172 + c + 1] = acc[mt][nt][3] + b1;
        }
    __syncthreads();

    // coalesced write: warp handles 16 rows
    #pragma unroll 1
    for(int i=0;i<16;i++){
        int r = warp*16 + i;
        long gr = m0 + r;
        float4* dst = reinterpret_cast<float4*>(g_prj + gr*160);
        const float4* src = reinterpret_cast<const float4*>(Pt + r*172);
        dst[lane] = src[lane];
        if(lane < 8) dst[32+lane] = src[32+lane];
    }
}

// ================= kernel 2b: bidirectional SSM scan =================
__global__ void __launch_bounds__(128)
k2b(const float* __restrict__ A_log_f, const float* __restrict__ D_f,
    const float* __restrict__ A_log_b, const float* __restrict__ D_b){
    __shared__ float hs[TT*DM];      // 768
    __shared__ float prj[TT*160];    // 1920

    const int tid = threadIdx.x;
    const int b = blockIdx.x;

    const float* hrow = g_h + (long)b*TT*DM;
    for(int i=tid;i<TT*DM;i+=128) hs[i] = hrow[i];
    const float* prow = g_prj + (long)b*TT*160;
    for(int i=tid;i<TT*160;i+=128) prj[i] = prow[i];
    __syncthreads();

    const int dir = tid >> 6;     // 0 fwd, 1 bwd
    const int d = tid & 63;
    const float* Alog = dir ? A_log_b : A_log_f;
    float Arow[DSS];
    #pragma unroll
    for(int n=0;n<DSS;n++) Arow[n] = -expf(Alog[d*DSS+n]);
    const float Dd = dir ? D_b[d] : D_f[d];
    float h[DSS];
    #pragma unroll
    for(int n=0;n<DSS;n++) h[n]=0.0f;
    float* yout = g_y + (long)b*TT*128 + dir*64 + d;
    const int joff = dir ? 80 : 0;

    for(int s=0;s<TT;s++){
        int t = dir ? (TT-1-s) : s;
        const float* p = prj + t*160 + joff;
        float delta = softplusf(p[d]);
        float x = hs[t*64 + d];
        float dx = delta * x;
        float y = 0.0f;
        #pragma unroll
        for(int n=0;n<DSS;n++){
            float dA = __expf(delta * Arow[n]);
            h[n] = dA*h[n] + dx*p[64+n];     // Bc
            y += h[n]*p[72+n];               // Cc
        }
        yout[t*128] = y + x*Dd;
    }
}

// ================= kernel 3: merge GEMM + LN + out GEMM (all tf32 TC) =================
// smem layout (floats):
//  Ys  [0,16896)      128x132  (phase-A A; then Ht stride 72; then part of Pg stage)
//  Wsm [16896,26112)  128x72
//  pad [26112,31744)                    (Pg stage = [0,31744) stride 248)
//  Wos [31744,47616)  64x248
//  Ah  [47616,56320)  128x68
//  bm 56320  lgs 56384  lbs 56448  bo 56512..56752
__global__ void __launch_bounds__(256)
k3(const float* __restrict__ W_merge, const float* __restrict__ b_merge,
   const float* __restrict__ lgm, const float* __restrict__ lbm,
   const float* __restrict__ W_out, const float* __restrict__ b_out,
   float* __restrict__ out){
    extern __shared__ float sm[];
    float* Ys  = sm;
    float* Wsm = sm + 16896;
    float* Wos = sm + 31744;
    float* Ah  = sm + 47616;
    float* bm  = sm + 56320;
    float* lgs = sm + 56384;
    float* lbs = sm + 56448;
    float* bo  = sm + 56512;

    const int tid = threadIdx.x, lane = tid & 31, warp = tid >> 5;
    const int gid = lane >> 2, tig = lane & 3;
    const long m0 = (long)blockIdx.x * 128;

    // ---- loads ----
    {   // Y tile [128x128] row-major stride 132
        int n4 = tid & 31, r0 = tid >> 5;
        #pragma unroll
        for(int r=r0; r<128; r+=8){
            float4 v = *reinterpret_cast<const float4*>(g_y + (m0+r)*128 + n4*4);
            float4 w; w.x=tf32r(v.x); w.y=tf32r(v.y); w.z=tf32r(v.z); w.w=tf32r(v.w);
            *reinterpret_cast<float4*>(Ys + r*132 + n4*4) = w;
        }
    }
    {   // W_merge [128x64] k-major stride 72
        int n4 = tid & 15, r0 = tid >> 4;
        #pragma unroll
        for(int r=r0; r<128; r+=16){
            float4 v = *reinterpret_cast<const float4*>(W_merge + r*64 + n4*4);
            float4 w; w.x=tf32r(v.x); w.y=tf32r(v.y); w.z=tf32r(v.z); w.w=tf32r(v.w);
            *reinterpret_cast<float4*>(Wsm + r*72 + n4*4) = w;
        }
    }
    // W_out [64x234] -> stride 248, zero the pad columns first
    for(int i=tid;i<64*248;i+=256) Wos[i] = 0.0f;
    __syncthreads();
    for(int i=tid;i<64*NC;i+=256) Wos[(i/NC)*248 + (i%NC)] = tf32r(W_out[i]);
    if(tid<64){ bm[tid]=b_merge[tid]; lgs[tid]=lgm[tid]; lbs[tid]=lbm[tid]; }
    for(int i=tid;i<NC;i+=256) bo[i] = b_out[i];
    __syncthreads();

    // ---- phase A: C1[128x64] = Y @ Wm ----
    {
        const int wm = warp & 3, wn = warp >> 2;    // 4m x 2n, warp tile 32x32
        float acc[2][4][4];
        #pragma unroll
        for(int a=0;a<2;a++)
            #pragma unroll
            for(int b=0;b<4;b++)
                #pragma unroll
                for(int q=0;q<4;q++) acc[a][b][q]=0.0f;

        #pragma unroll
        for(int kk=0;kk<128;kk+=8){
            uint32_t af[2][4];
            #pragma unroll
            for(int mt=0;mt<2;mt++){
                int m = wm*32 + mt*16 + gid;
                af[mt][0] = __float_as_uint(Ys[ m   *132 + kk+tig  ]);
                af[mt][1] = __float_as_uint(Ys[(m+8)*132 + kk+tig  ]);
                af[mt][2] = __float_as_uint(Ys[ m   *132 + kk+tig+4]);
                af[mt][3] = __float_as_uint(Ys[(m+8)*132 + kk+tig+4]);
            }
            #pragma unroll
            for(int nt=0;nt<4;nt++){
                int n = wn*32 + nt*8 + gid;
                uint32_t bf[2];
                bf[0] = __float_as_uint(Wsm[(kk+tig  )*72 + n]);
                bf[1] = __float_as_uint(Wsm[(kk+tig+4)*72 + n]);
                #pragma unroll
                for(int mt=0;mt<2;mt++) mma8(acc[mt][nt], af[mt], bf);
            }
        }
        __syncthreads();          // all Ys reads done before reuse as Ht

        float* Ht = Ys;           // stride 72
        #pragma unroll
        for(int mt=0;mt<2;mt++)
            #pragma unroll
            for(int nt=0;nt<4;nt++){
                int r = wm*32 + mt*16 + gid;
                int c = wn*32 + nt*8 + 2*tig;
                Ht[ r   *72 + c    ] = acc[mt][nt][0];
                Ht[ r   *72 + c + 1] = acc[mt][nt][1];
                Ht[(r+8)*72 + c    ] = acc[mt][nt][2];
                Ht[(r+8)*72 + c + 1] = acc[mt][nt][3];
            }
        __syncthreads();
    }

    // ---- LN epilogue: Ah = tf32(LN(C1 + bm + residual)) ----
    {
        float* Ht = Ys;
        const float b0 = bm[lane], b1 = bm[lane+32];
        const float gg0 = lgs[lane], gg1 = lgs[lane+32];
        const float ee0 = lbs[lane], ee1 = lbs[lane+32];
        #pragma unroll 1
        for(int i=0;i<16;i++){
            int r = warp*16 + i;
            long gr = m0 + r;
            float v0 = Ht[r*72 + lane   ] + b0 + g_h[gr*64 + lane   ];
            float v1 = Ht[r*72 + lane+32] + b1 + g_h[gr*64 + lane+32];
            float mu = warp_sum(v0+v1) * (1.0f/64.0f);
            float d0 = v0-mu, d1 = v1-mu;
            float var = warp_sum(d0*d0 + d1*d1) * (1.0f/64.0f);
            float rs = rsqrtf(var + 1e-5f);
            Ah[r*68 + lane   ] = tf32r(d0*rs*gg0 + ee0);
            Ah[r*68 + lane+32] = tf32r(d1*rs*gg1 + ee1);
        }
        __syncthreads();
    }

    // ---- phase B: out[128x234] = Ah @ Wo ----
    {
        const int wm2 = warp & 1, wn2 = warp >> 1;   // 2m x 4n, warp tile 64x64
        float acc2[4][8][4];
        #pragma unroll
        for(int a=0;a<4;a++)
            #pragma unroll
            for(int b=0;b<8;b++)
                #pragma unroll
                for(int q=0;q<4;q++) acc2[a][b][q]=0.0f;

        #pragma unroll
        for(int kk=0;kk<64;kk+=8){
            uint32_t af[4][4];
            #pragma unroll
            for(int mt=0;mt<4;mt++){
                int m = wm2*64 + mt*16 + gid;
                af[mt][0] = __float_as_uint(Ah[ m   *68 + kk+tig  ]);
                af[mt][1] = __float_as_uint(Ah[(m+8)*68 + kk+tig  ]);
                af[mt][2] = __float_as_uint(Ah[ m   *68 + kk+tig+4]);
                af[mt][3] = __float_as_uint(Ah[(m+8)*68 + kk+tig+4]);
            }
            #pragma unroll
            for(int nt=0;nt<8;nt++){
                int n = wn2*64 + nt*8 + gid;
                uint32_t bf[2];
                bf[0] = __float_as_uint(Wos[(kk+tig  )*248 + n]);
                bf[1] = __float_as_uint(Wos[(kk+tig+4)*248 + n]);
                #pragma unroll
                for(int mt=0;mt<4;mt++) mma8(acc2[mt][nt], af[mt], bf);
            }
        }
        __syncthreads();   // Ah reads done; Pg stage region free

        float* Pg = sm;    // stride 248, rows 128 -> [0,31744)
        #pragma unroll
        for(int mt=0;mt<4;mt++)
            #pragma unroll
            for(int nt=0;nt<8;nt++){
                int r = wm2*64 + mt*16 + gid;
                int c = wn2*64 + nt*8 + 2*tig;
                if(c < NC){
                    float b0 = bo[c], b1 = (c+1<NC) ? bo[c+1] : 0.0f;
                    Pg[ r   *248 + c    ] = acc2[mt][nt][0] + b0;
                    Pg[ r   *248 + c + 1] = acc2[mt][nt][1] + b1;
                    Pg[(r+8)*248 + c    ] = acc2[mt][nt][2] + b0;
                    Pg[(r+8)*248 + c + 1] = acc2[mt][nt][3] + b1;
                }
            }
        __syncthreads();

        // coalesced store: warp handles 16 rows
        #pragma unroll 1
        for(int i=0;i<16;i++){
            int r = warp*16 + i;
            long gr = m0 + r;
            #pragma unroll
            for(int q=0;q<8;q++){
                int j = lane + 32*q;
                if(j < NC) out[gr*NC + j] = Pg[r*248 + j];
            }
        }
    }
}

// ================= launch =================
extern "C" void kernel_launch(void* const* d_in, const int* in_sizes, int n_in,
                              void* d_out, int out_size){
    const float* emb      = (const float*)d_in[0];
    const float* scores   = (const float*)d_in[1];
    const int*   site_ids = (const int*)  d_in[2];
    const int*   hours    = (const int*)  d_in[3];
    const float* W_in     = (const float*)d_in[4];
    const float* b_in     = (const float*)d_in[5];
    const float* ln_in_g  = (const float*)d_in[6];
    const float* ln_in_b  = (const float*)d_in[7];
    const float* site_emb = (const float*)d_in[8];
    const float* hour_emb = (const float*)d_in[9];
    const float* W_meta   = (const float*)d_in[10];
    const float* b_meta   = (const float*)d_in[11];
    const float* pos_enc  = (const float*)d_in[12];
    const float* A_log_f  = (const float*)d_in[13];
    const float* Wp_f     = (const float*)d_in[14];
    const float* bp_f     = (const float*)d_in[15];
    const float* D_f      = (const float*)d_in[16];
    const float* A_log_b  = (const float*)d_in[17];
    const float* Wp_b     = (const float*)d_in[18];
    const float* bp_b     = (const float*)d_in[19];
    const float* D_b      = (const float*)d_in[20];
    const float* W_merge  = (const float*)d_in[21];
    const float* b_merge  = (const float*)d_in[22];
    const float* ln_g     = (const float*)d_in[23];
    const float* ln_b     = (const float*)d_in[24];
    const float* W_out    = (const float*)d_in[25];
    const float* b_out    = (const float*)d_in[26];
    float* out = (float*)d_out;

    cudaFuncSetAttribute(k1,  cudaFuncAttributeMaxDynamicSharedMemorySize, 53248);
    cudaFuncSetAttribute(k2a, cudaFuncAttributeMaxDynamicSharedMemorySize, 166528);
    cudaFuncSetAttribute(k3,  cudaFuncAttributeMaxDynamicSharedMemorySize, 227008);

    k_meta<<<(BATCH*DM)/256, 256>>>(site_ids, hours, site_emb, hour_emb, W_meta, b_meta);
    k1<<<NROWS/128, 256, 53248>>>(emb, scores, W_in, b_in, ln_in_g, ln_in_b, pos_enc);
    k2a<<<NROWS/128, 256, 166528>>>(Wp_f, bp_f, Wp_b, bp_b);
    k2b<<<BATCH, 128>>>(A_log_f, D_f, A_log_b, D_b);
    k3<<<NROWS/128, 256, 227008>>>(W_merge, b_merge, ln_g, ln_b, W_out, b_out, out);
}

// round 8
// speedup vs baseline: 1.9888x; 1.1476x over previous
#include <cuda_runtime.h>
#include <cstdint>
#include <math.h>

#define BATCH  4096
#define TT     12
#define NROWS  (BATCH*TT)       // 49152
#define DIN    1536
#define DSC    234
#define KTOT   1770
#define KTILES 56               // padded K = 1792
#define DM     64
#define DSS    8
#define NC     234
#define NSITES 20

// ---------------- scratch ----------------
__device__ float g_h[NROWS*DM];        // residual after stage 1
__device__ float g_y[NROWS*2*DM];      // concat(h_f, h_b)
__device__ float g_meta[BATCH*DM];
__device__ float g_prj[NROWS*160];     // proj (fwd 0:80 | bwd 80:160), bias included
__device__ float g_wt[1792*64];        // W_in pre-rounded to tf32, zero-padded rows
__device__ float g_An[1024];           // -exp(A_log): [dir][d][n]
__device__ float g_Dc[128];            // [dir][d]

// ---------------- helpers ----------------
__device__ __forceinline__ float tf32r(float x){
    float r; asm("cvt.rna.tf32.f32 %0, %1;" : "=f"(r) : "f"(x)); return r;
}
__device__ __forceinline__ void mma8(float* c, const uint32_t* a, const uint32_t* b){
    asm volatile("mma.sync.aligned.m16n8k8.row.col.f32.tf32.tf32.f32 "
        "{%0,%1,%2,%3},{%4,%5,%6,%7},{%8,%9},{%0,%1,%2,%3};\n"
        : "+f"(c[0]),"+f"(c[1]),"+f"(c[2]),"+f"(c[3])
        : "r"(a[0]),"r"(a[1]),"r"(a[2]),"r"(a[3]),"r"(b[0]),"r"(b[1]));
}
__device__ __forceinline__ float warp_sum(float v){
    #pragma unroll
    for(int o=16;o;o>>=1) v += __shfl_xor_sync(0xffffffffu, v, o);
    return v;
}
__device__ __forceinline__ float gelu_exact(float x){
    return 0.5f*x*(1.0f + erff(x*0.70710678118654752f));
}
__device__ __forceinline__ uint32_t s2u(const void* p){
    uint32_t a; asm("{ .reg .u64 t; cvta.to.shared.u64 t, %1; cvt.u32.u64 %0, t; }" : "=r"(a) : "l"(p));
    return a;
}
__device__ __forceinline__ void cpa16(uint32_t dst, const void* src){
    asm volatile("cp.async.cg.shared.global [%0], [%1], 16;\n" :: "r"(dst), "l"(src));
}
__device__ __forceinline__ void cpa8z(uint32_t dst, const void* src, int bytes){
    asm volatile("cp.async.ca.shared.global [%0], [%1], 8, %2;\n" :: "r"(dst), "l"(src), "r"(bytes));
}
__device__ __forceinline__ void cpcommit(){ asm volatile("cp.async.commit_group;\n" ::: "memory"); }
template<int N> __device__ __forceinline__ void cpwait(){ asm volatile("cp.async.wait_group %0;\n" :: "n"(N) : "memory"); }

// ================= prep: W tf32-round + A/D precompute =================
__global__ void k_prep(const float* __restrict__ W_in,
                       const float* __restrict__ A_log_f, const float* __restrict__ A_log_b,
                       const float* __restrict__ D_f, const float* __restrict__ D_b){
    int i = blockIdx.x*256 + threadIdx.x;
    if(i < 1792*64){
        int k = i >> 6;
        g_wt[i] = (k < KTOT) ? tf32r(W_in[i]) : 0.0f;
    }
    if(i < 1024){
        int dir = i >> 9, rem = i & 511;
        const float* Al = dir ? A_log_b : A_log_f;
        g_An[i] = -expf(Al[rem]);
    }
    if(i < 128){
        g_Dc[i] = (i < 64) ? D_f[i] : D_b[i-64];
    }
}

// ================= kernel 0: meta embedding GEMM =================
__global__ void k_meta(const int* __restrict__ site_ids, const int* __restrict__ hours,
                       const float* __restrict__ site_emb, const float* __restrict__ hour_emb,
                       const float* __restrict__ W_meta, const float* __restrict__ b_meta){
    int idx = blockIdx.x*blockDim.x + threadIdx.x;
    int b = idx >> 6, d = idx & 63;
    int s = site_ids[b]; s = min(max(s,0), NSITES-1);
    int hh = hours[b];   hh = min(max(hh,0), 23);
    float acc = b_meta[d];
    #pragma unroll
    for(int j=0;j<8;j++){
        acc += site_emb[s*8+j]*W_meta[j*64+d];
        acc += hour_emb[hh*8+j]*W_meta[(8+j)*64+d];
    }
    g_meta[idx] = acc;
}

// ================= kernel 1: big GEMM (tf32, cp.async 4-stage) + LN + gelu =================
// stage = A[128x36] (4608 fl) + W[32x72] (2304 fl) = 6912 fl; 4 stages = 110592 B
#define K1_STG 6912

__global__ void __launch_bounds__(256)
k1(const float* __restrict__ emb, const float* __restrict__ scores,
   const float* __restrict__ b_in,
   const float* __restrict__ lg, const float* __restrict__ lb,
   const float* __restrict__ pos_enc){
    extern __shared__ float sm[];

    const int tid = threadIdx.x, lane = tid & 31, warp = tid >> 5;
    const int gid = lane >> 2, tig = lane & 3;
    const int wm = warp & 3, wn = warp >> 2;
    const long m0 = (long)blockIdx.x * 128;

    const int arow_l = tid & 127;       // A row this thread loads
    const int half   = tid >> 7;        // which 16-col half
    const long arow  = m0 + arow_l;
    const float* embrow = emb + arow*DIN;
    const float* scrow  = scores + arow*DSC;
    const int wrow = tid >> 3, wc8 = (tid & 7)*8;
    const uint32_t smb = s2u(sm);

    float acc[2][4][4];
    #pragma unroll
    for(int i=0;i<2;i++)
        #pragma unroll
        for(int j=0;j<4;j++)
            #pragma unroll
            for(int q=0;q<4;q++) acc[i][j][q]=0.0f;

    auto issue_tile = [&](int ki){
        int st = ki & 3;
        // A tile
        uint32_t ab = smb + (uint32_t)st*K1_STG*4 + arow_l*144 + half*64;
        if(ki < 48){
            const float* src = embrow + ki*32 + half*16;
            cpa16(ab,    src   );
            cpa16(ab+16, src+4 );
            cpa16(ab+32, src+8 );
            cpa16(ab+48, src+12);
        } else {
            int sbase = ki*32 + half*16 - DIN;
            #pragma unroll
            for(int j=0;j<8;j++){
                int s = sbase + j*2;
                int v = DSC - s; v = v<0 ? 0 : (v>2 ? 2 : v);
                cpa8z(ab + j*8, scrow + (v>0 ? s : 0), v*4);
            }
        }
        // W tile
        uint32_t wb = smb + ((uint32_t)st*K1_STG + 4608)*4 + wrow*288 + wc8*4;
        const float* wsrc = g_wt + (ki*32 + wrow)*64 + wc8;
        cpa16(wb,    wsrc  );
        cpa16(wb+16, wsrc+4);
    };

    // prologue: tiles 0,1,2 (one commit group each)
    issue_tile(0); cpcommit();
    issue_tile(1); cpcommit();
    issue_tile(2); cpcommit();

    for(int ki=0; ki<KTILES; ki++){
        cpwait<2>();
        __syncthreads();

        const float* As = sm + (ki & 3)*K1_STG;          // [128][36]
        const float* Ws = sm + (ki & 3)*K1_STG + 4608;   // [32][72]

        #pragma unroll
        for(int kk=0;kk<32;kk+=8){
            uint32_t af[2][4];
            #pragma unroll
            for(int mt=0;mt<2;mt++){
                int m = wm*32 + mt*16 + gid;
                af[mt][0] = __float_as_uint(As[ m   *36 + kk+tig  ]);
                af[mt][1] = __float_as_uint(As[(m+8)*36 + kk+tig  ]);
                af[mt][2] = __float_as_uint(As[ m   *36 + kk+tig+4]);
                af[mt][3] = __float_as_uint(As[(m+8)*36 + kk+tig+4]);
            }
            #pragma unroll
            for(int nt=0;nt<4;nt++){
                int n = wn*32 + nt*8 + gid;
                uint32_t bf[2];
                bf[0] = __float_as_uint(Ws[(kk+tig  )*72 + n]);
                bf[1] = __float_as_uint(Ws[(kk+tig+4)*72 + n]);
                #pragma unroll
                for(int mt=0;mt<2;mt++) mma8(acc[mt][nt], af[mt], bf);
            }
        }
        if(ki+3 < KTILES) issue_tile(ki+3);
        cpcommit();   // always commit (possibly empty) to keep group count in lockstep
    }

    cpwait<0>();
    __syncthreads();

    // scatter accumulators into smem tile (stride 72), reuse stage memory
    float* Ht = sm;
    #pragma unroll
    for(int mt=0;mt<2;mt++)
        #pragma unroll
        for(int nt=0;nt<4;nt++){
            int r = wm*32 + mt*16 + gid;
            int c = wn*32 + nt*8 + 2*tig;
            Ht[ r   *72 + c    ] = acc[mt][nt][0];
            Ht[ r   *72 + c + 1] = acc[mt][nt][1];
            Ht[(r+8)*72 + c    ] = acc[mt][nt][2];
            Ht[(r+8)*72 + c + 1] = acc[mt][nt][3];
        }
    __syncthreads();

    const float bin0 = b_in[lane], bin1 = b_in[lane+32];
    const float gg0 = lg[lane], gg1 = lg[lane+32];
    const float ee0 = lb[lane], ee1 = lb[lane+32];
    #pragma unroll 1
    for(int i=0;i<16;i++){
        int r = warp*16 + i;
        float v0 = Ht[r*72 + lane   ] + bin0;
        float v1 = Ht[r*72 + lane+32] + bin1;
        float mu = warp_sum(v0+v1) * (1.0f/64.0f);
        float d0 = v0-mu, d1 = v1-mu;
        float var = warp_sum(d0*d0 + d1*d1) * (1.0f/64.0f);
        float rs = rsqrtf(var + 1e-5f);
        float y0 = gelu_exact(d0*rs*gg0 + ee0);
        float y1 = gelu_exact(d1*rs*gg1 + ee1);
        long grow = m0 + r;
        int bb = (int)(grow / TT), tt2 = (int)(grow % TT);
        y0 += g_meta[bb*64 + lane   ] + pos_enc[tt2*64 + lane   ];
        y1 += g_meta[bb*64 + lane+32] + pos_enc[tt2*64 + lane+32];
        g_h[grow*64 + lane   ] = y0;
        g_h[grow*64 + lane+32] = y1;
    }
}

// ================= kernel 2a: proj GEMM (tf32 TC) =================
// smem: Hs [0,8704) s68 | Wps [8704,19456) s168 | Pt [0,22016) s172 (reuse) | bps [22016,22176)
__global__ void __launch_bounds__(256)
k2a(const float* __restrict__ Wp_f, const float* __restrict__ bp_f,
    const float* __restrict__ Wp_b, const float* __restrict__ bp_b){
    extern __shared__ float sm[];
    float* Hs  = sm;
    float* Wps = sm + 8704;
    float* Pt  = sm;
    float* bps = sm + 22016;

    const int tid = threadIdx.x, lane = tid & 31, warp = tid >> 5;
    const int gid = lane >> 2, tig = lane & 3;
    const int wm = warp & 3, wn = warp >> 2;       // warp tile 32x80
    const long m0 = (long)blockIdx.x * 128;

    {
        int n4 = tid & 15, r0 = tid >> 4;
        #pragma unroll
        for(int r=r0; r<128; r+=16){
            float4 v = *reinterpret_cast<const float4*>(g_h + (m0+r)*64 + n4*4);
            float4 w; w.x=tf32r(v.x); w.y=tf32r(v.y); w.z=tf32r(v.z); w.w=tf32r(v.w);
            *reinterpret_cast<float4*>(Hs + r*68 + n4*4) = w;
        }
    }
    for(int i=tid;i<64*160;i+=256){
        int k = i/160, j = i%160;
        Wps[k*168+j] = tf32r((j<80) ? Wp_f[k*80+j] : Wp_b[k*80+(j-80)]);
    }
    for(int i=tid;i<160;i+=256) bps[i] = (i<80) ? bp_f[i] : bp_b[i-80];
    __syncthreads();

    float acc[2][10][4];
    #pragma unroll
    for(int a=0;a<2;a++)
        #pragma unroll
        for(int b=0;b<10;b++)
            #pragma unroll
            for(int q=0;q<4;q++) acc[a][b][q]=0.0f;

    #pragma unroll
    for(int kk=0;kk<64;kk+=8){
        uint32_t af[2][4];
        #pragma unroll
        for(int mt=0;mt<2;mt++){
            int m = wm*32 + mt*16 + gid;
            af[mt][0] = __float_as_uint(Hs[ m   *68 + kk+tig  ]);
            af[mt][1] = __float_as_uint(Hs[(m+8)*68 + kk+tig  ]);
            af[mt][2] = __float_as_uint(Hs[ m   *68 + kk+tig+4]);
            af[mt][3] = __float_as_uint(Hs[(m+8)*68 + kk+tig+4]);
        }
        #pragma unroll
        for(int nt=0;nt<10;nt++){
            int n = wn*80 + nt*8 + gid;
            uint32_t bf[2];
            bf[0] = __float_as_uint(Wps[(kk+tig  )*168 + n]);
            bf[1] = __float_as_uint(Wps[(kk+tig+4)*168 + n]);
            #pragma unroll
            for(int mt=0;mt<2;mt++) mma8(acc[mt][nt], af[mt], bf);
        }
    }
    __syncthreads();   // Hs/Wps reads complete before Pt overwrite

    #pragma unroll
    for(int mt=0;mt<2;mt++)
        #pragma unroll
        for(int nt=0;nt<10;nt++){
            int r = wm*32 + mt*16 + gid;
            int c = wn*80 + nt*8 + 2*tig;
            float b0 = bps[c], b1 = bps[c+1];
            Pt[ r   *172 + c    ] = acc[mt][nt][0] + b0;
            Pt[ r   *172 + c + 1] = acc[mt][nt][1] + b1;
            Pt[(r+8)*172 + c    ] = acc[mt][nt][2] + b0;
            Pt[(r+8)*172 + c + 1] = acc[mt][nt][3] + b1;
        }
    __syncthreads();

    #pragma unroll 1
    for(int i=0;i<16;i++){
        int r = warp*16 + i;
        long gr = m0 + r;
        float4* dst = reinterpret_cast<float4*>(g_prj + gr*160);
        const float4* src = reinterpret_cast<const float4*>(Pt + r*172);
        dst[lane] = src[lane];
        if(lane < 8) dst[32+lane] = src[32+lane];
    }
}

// ================= kernel 2b: bidirectional SSM scan (4 batches/CTA) =================
__global__ void __launch_bounds__(512)
k2b(){
    __shared__ float hs[4*768];
    __shared__ float prj[4*1920];

    const int tid = threadIdx.x;
    const long b0 = (long)blockIdx.x * 4;

    const float* hsrc = g_h + b0*768;
    for(int i=tid;i<4*768;i+=512) hs[i] = hsrc[i];
    const float* psrc = g_prj + b0*1920;
    for(int i=tid;i<4*1920;i+=512) prj[i] = psrc[i];
    __syncthreads();

    const int lb  = tid >> 7;          // local batch 0..3
    const int dir = (tid >> 6) & 1;
    const int d   = tid & 63;

    float Arow[DSS];
    #pragma unroll
    for(int n=0;n<DSS;n++) Arow[n] = g_An[dir*512 + d*8 + n];
    const float Dd = g_Dc[dir*64 + d];

    float h[DSS];
    #pragma unroll
    for(int n=0;n<DSS;n++) h[n]=0.0f;

    const float* hsb = hs + lb*768;
    const float* pb  = prj + lb*1920;
    float* yout = g_y + (b0+lb)*TT*128 + dir*64 + d;
    const int joff = dir ? 80 : 0;

    for(int s=0;s<TT;s++){
        int t = dir ? (TT-1-s) : s;
        const float* p = pb + t*160 + joff;
        float pd = p[d];
        float delta = (pd > 15.0f) ? pd : __logf(1.0f + __expf(pd));
        float x = hsb[t*64 + d];
        float dx = delta * x;
        float y = 0.0f;
        #pragma unroll
        for(int n=0;n<DSS;n++){
            float dA = __expf(delta * Arow[n]);
            h[n] = dA*h[n] + dx*p[64+n];
            y = fmaf(h[n], p[72+n], y);
        }
        yout[t*128] = y + x*Dd;
    }
}

// ================= kernel 3: merge GEMM + LN + out GEMM (512 threads) =================
// smem: Ys [0,16896) s132 | Wsm [16896,26112) s72 | Wos [26112,43008) s264
//       Ah [43008,51712) s68 | bm 51712 | lgs 51776 | lbs 51840 | bo 51904..52144
//       Ht reuse [0,9216) s72 | Pg reuse [0,33792) s264
__global__ void __launch_bounds__(512)
k3(const float* __restrict__ W_merge, const float* __restrict__ b_merge,
   const float* __restrict__ lgm, const float* __restrict__ lbm,
   const float* __restrict__ W_out, const float* __restrict__ b_out,
   float* __restrict__ out){
    extern __shared__ float sm[];
    float* Ys  = sm;
    float* Wsm = sm + 16896;
    float* Wos = sm + 26112;
    float* Ah  = sm + 43008;
    float* bm  = sm + 51712;
    float* lgs = sm + 51776;
    float* lbs = sm + 51840;
    float* bo  = sm + 51904;

    const int tid = threadIdx.x, lane = tid & 31, warp = tid >> 5;
    const int gid = lane >> 2, tig = lane & 3;
    const long m0 = (long)blockIdx.x * 128;

    {   // Y tile [128x128] stride 132
        int n4 = tid & 31, r0 = tid >> 5;
        #pragma unroll
        for(int r=r0; r<128; r+=16){
            float4 v = *reinterpret_cast<const float4*>(g_y + (m0+r)*128 + n4*4);
            float4 w; w.x=tf32r(v.x); w.y=tf32r(v.y); w.z=tf32r(v.z); w.w=tf32r(v.w);
            *reinterpret_cast<float4*>(Ys + r*132 + n4*4) = w;
        }
    }
    {   // W_merge [128x64] stride 72
        int n4 = tid & 15, r0 = tid >> 4;
        #pragma unroll
        for(int r=r0; r<128; r+=32){
            float4 v = *reinterpret_cast<const float4*>(W_merge + r*64 + n4*4);
            float4 w; w.x=tf32r(v.x); w.y=tf32r(v.y); w.z=tf32r(v.z); w.w=tf32r(v.w);
            *reinterpret_cast<float4*>(Wsm + r*72 + n4*4) = w;
        }
    }
    for(int i=tid;i<64*264;i+=512) Wos[i] = 0.0f;
    __syncthreads();
    for(int i=tid;i<64*NC;i+=512) Wos[(i/NC)*264 + (i%NC)] = tf32r(W_out[i]);
    if(tid<64){ bm[tid]=b_merge[tid]; lgs[tid]=lgm[tid]; lbs[tid]=lbm[tid]; }
    for(int i=tid;i<NC;i+=512) bo[i] = b_out[i];
    __syncthreads();

    // ---- phase A: C1[128x64] = Y @ Wm  (16 warps, warp tile 32x16) ----
    {
        const int wm = warp & 3, wn = warp >> 2;   // wn 0..3
        float acc[2][2][4];
        #pragma unroll
        for(int a=0;a<2;a++)
            #pragma unroll
            for(int b=0;b<2;b++)
                #pragma unroll
                for(int q=0;q<4;q++) acc[a][b][q]=0.0f;

        #pragma unroll
        for(int kk=0;kk<128;kk+=8){
            uint32_t af[2][4];
            #pragma unroll
            for(int mt=0;mt<2;mt++){
                int m = wm*32 + mt*16 + gid;
                af[mt][0] = __float_as_uint(Ys[ m   *132 + kk+tig  ]);
                af[mt][1] = __float_as_uint(Ys[(m+8)*132 + kk+tig  ]);
                af[mt][2] = __float_as_uint(Ys[ m   *132 + kk+tig+4]);
                af[mt][3] = __float_as_uint(Ys[(m+8)*132 + kk+tig+4]);
            }
            #pragma unroll
            for(int nt=0;nt<2;nt++){
                int n = wn*16 + nt*8 + gid;
                uint32_t bf[2];
                bf[0] = __float_as_uint(Wsm[(kk+tig  )*72 + n]);
                bf[1] = __float_as_uint(Wsm[(kk+tig+4)*72 + n]);
                #pragma unroll
                for(int mt=0;mt<2;mt++) mma8(acc[mt][nt], af[mt], bf);
            }
        }
        __syncthreads();          // Ys reads done before Ht overwrite

        float* Ht = sm;           // stride 72
        #pragma unroll
        for(int mt=0;mt<2;mt++)
            #pragma unroll
            for(int nt=0;nt<2;nt++){
                int r = wm*32 + mt*16 + gid;
                int c = wn*16 + nt*8 + 2*tig;
                Ht[ r   *72 + c    ] = acc[mt][nt][0];
                Ht[ r   *72 + c + 1] = acc[mt][nt][1];
                Ht[(r+8)*72 + c    ] = acc[mt][nt][2];
                Ht[(r+8)*72 + c + 1] = acc[mt][nt][3];
            }
        __syncthreads();
    }

    // ---- LN: Ah = tf32(LN(C1 + bm + residual)) ----
    {
        float* Ht = sm;
        const float b0 = bm[lane], b1 = bm[lane+32];
        const float gg0 = lgs[lane], gg1 = lgs[lane+32];
        const float ee0 = lbs[lane], ee1 = lbs[lane+32];
        #pragma unroll 1
        for(int i=0;i<8;i++){
            int r = warp*8 + i;
            long gr = m0 + r;
            float v0 = Ht[r*72 + lane   ] + b0 + g_h[gr*64 + lane   ];
            float v1 = Ht[r*72 + lane+32] + b1 + g_h[gr*64 + lane+32];
            float mu = warp_sum(v0+v1) * (1.0f/64.0f);
            float d0 = v0-mu, d1 = v1-mu;
            float var = warp_sum(d0*d0 + d1*d1) * (1.0f/64.0f);
            float rs = rsqrtf(var + 1e-5f);
            Ah[r*68 + lane   ] = tf32r(d0*rs*gg0 + ee0);
            Ah[r*68 + lane+32] = tf32r(d1*rs*gg1 + ee1);
        }
        __syncthreads();
    }

    // ---- phase B: out = Ah @ Wo  (16 warps, warp tile 64x32) ----
    {
        const int wm2 = warp & 1, wn2 = warp >> 1;   // wn2 0..7
        float acc2[4][4][4];
        #pragma unroll
        for(int a=0;a<4;a++)
            #pragma unroll
            for(int b=0;b<4;b++)
                #pragma unroll
                for(int q=0;q<4;q++) acc2[a][b][q]=0.0f;

        #pragma unroll
        for(int kk=0;kk<64;kk+=8){
            uint32_t af[4][4];
            #pragma unroll
            for(int mt=0;mt<4;mt++){
                int m = wm2*64 + mt*16 + gid;
                af[mt][0] = __float_as_uint(Ah[ m   *68 + kk+tig  ]);
                af[mt][1] = __float_as_uint(Ah[(m+8)*68 + kk+tig  ]);
                af[mt][2] = __float_as_uint(Ah[ m   *68 + kk+tig+4]);
                af[mt][3] = __float_as_uint(Ah[(m+8)*68 + kk+tig+4]);
            }
            #pragma unroll
            for(int nt=0;nt<4;nt++){
                int n = wn2*32 + nt*8 + gid;
                uint32_t bf[2];
                bf[0] = __float_as_uint(Wos[(kk+tig  )*264 + n]);
                bf[1] = __float_as_uint(Wos[(kk+tig+4)*264 + n]);
                #pragma unroll
                for(int mt=0;mt<4;mt++) mma8(acc2[mt][nt], af[mt], bf);
            }
        }
        __syncthreads();   // Ah/Wos reads done; Pg region free

        float* Pg = sm;    // stride 264
        #pragma unroll
        for(int mt=0;mt<4;mt++)
            #pragma unroll
            for(int nt=0;nt<4;nt++){
                int r = wm2*64 + mt*16 + gid;
                int c = wn2*32 + nt*8 + 2*tig;
                if(c < NC){
                    float b0 = bo[c], b1 = (c+1<NC) ? bo[c+1] : 0.0f;
                    Pg[ r   *264 + c    ] = acc2[mt][nt][0] + b0;
                    Pg[ r   *264 + c + 1] = acc2[mt][nt][1] + b1;
                    Pg[(r+8)*264 + c    ] = acc2[mt][nt][2] + b0;
                    Pg[(r+8)*264 + c + 1] = acc2[mt][nt][3] + b1;
                }
            }
        __syncthreads();

        #pragma unroll 1
        for(int i=0;i<8;i++){
            int r = warp*8 + i;
            long gr = m0 + r;
            #pragma unroll
            for(int q=0;q<8;q++){
                int j = lane + 32*q;
                if(j < NC) out[gr*NC + j] = Pg[r*264 + j];
            }
        }
    }
}

// ================= launch =================
extern "C" void kernel_launch(void* const* d_in, const int* in_sizes, int n_in,
                              void* d_out, int out_size){
    const float* emb      = (const float*)d_in[0];
    const float* scores   = (const float*)d_in[1];
    const int*   site_ids = (const int*)  d_in[2];
    const int*   hours    = (const int*)  d_in[3];
    const float* W_in     = (const float*)d_in[4];
    const float* b_in     = (const float*)d_in[5];
    const float* ln_in_g  = (const float*)d_in[6];
    const float* ln_in_b  = (const float*)d_in[7];
    const float* site_emb = (const float*)d_in[8];
    const float* hour_emb = (const float*)d_in[9];
    const float* W_meta   = (const float*)d_in[10];
    const float* b_meta   = (const float*)d_in[11];
    const float* pos_enc  = (const float*)d_in[12];
    const float* A_log_f  = (const float*)d_in[13];
    const float* Wp_f     = (const float*)d_in[14];
    const float* bp_f     = (const float*)d_in[15];
    const float* D_f      = (const float*)d_in[16];
    const float* A_log_b  = (const float*)d_in[17];
    const float* Wp_b     = (const float*)d_in[18];
    const float* bp_b     = (const float*)d_in[19];
    const float* D_b      = (const float*)d_in[20];
    const float* W_merge  = (const float*)d_in[21];
    const float* b_merge  = (const float*)d_in[22];
    const float* ln_g     = (const float*)d_in[23];
    const float* ln_b     = (const float*)d_in[24];
    const float* W_out    = (const float*)d_in[25];
    const float* b_out    = (const float*)d_in[26];
    float* out = (float*)d_out;

    cudaFuncSetAttribute(k1,  cudaFuncAttributeMaxDynamicSharedMemorySize, 110592);
    cudaFuncSetAttribute(k2a, cudaFuncAttributeMaxDynamicSharedMemorySize, 88704);
    cudaFuncSetAttribute(k3,  cudaFuncAttributeMaxDynamicSharedMemorySize, 208576);

    k_prep<<<448, 256>>>(W_in, A_log_f, A_log_b, D_f, D_b);
    k_meta<<<(BATCH*DM)/256, 256>>>(site_ids, hours, site_emb, hour_emb, W_meta, b_meta);
    k1<<<NROWS/128, 256, 110592>>>(emb, scores, b_in, ln_in_g, ln_in_b, pos_enc);
    k2a<<<NROWS/128, 256, 88704>>>(Wp_f, bp_f, Wp_b, bp_b);
    k2b<<<BATCH/4, 512>>>();
    k3<<<NROWS/128, 512, 208576>>>(W_merge, b_merge, ln_g, ln_b, W_out, b_out, out);
}

// round 9
// speedup vs baseline: 2.2015x; 1.1070x over previous
#include <cuda_runtime.h>
#include <cstdint>
#include <math.h>

#define BATCH  4096
#define TT     12
#define NROWS  (BATCH*TT)       // 49152
#define DIN    1536
#define DSC    234
#define KTOT   1770
#define KTILES 56               // padded K = 1792
#define DM     64
#define DSS    8
#define NC     234
#define NSITES 20

// ---------------- scratch ----------------
__device__ float g_h[NROWS*DM];        // residual after stage 1
__device__ float g_y[NROWS*2*DM];      // concat(h_f, h_b)
__device__ float g_meta[BATCH*DM];
__device__ float g_wt[1792*64];        // W_in pre-rounded to tf32, zero-padded rows
__device__ float g_An[1024];           // -exp(A_log): [dir][d][n]
__device__ float g_Dc[128];            // [dir][d]

// ---------------- helpers ----------------
__device__ __forceinline__ float tf32r(float x){
    float r; asm("cvt.rna.tf32.f32 %0, %1;" : "=f"(r) : "f"(x)); return r;
}
__device__ __forceinline__ void mma8(float* c, const uint32_t* a, const uint32_t* b){
    asm volatile("mma.sync.aligned.m16n8k8.row.col.f32.tf32.tf32.f32 "
        "{%0,%1,%2,%3},{%4,%5,%6,%7},{%8,%9},{%0,%1,%2,%3};\n"
        : "+f"(c[0]),"+f"(c[1]),"+f"(c[2]),"+f"(c[3])
        : "r"(a[0]),"r"(a[1]),"r"(a[2]),"r"(a[3]),"r"(b[0]),"r"(b[1]));
}
__device__ __forceinline__ float warp_sum(float v){
    #pragma unroll
    for(int o=16;o;o>>=1) v += __shfl_xor_sync(0xffffffffu, v, o);
    return v;
}
__device__ __forceinline__ float gelu_exact(float x){
    return 0.5f*x*(1.0f + erff(x*0.70710678118654752f));
}
__device__ __forceinline__ uint32_t s2u(const void* p){
    uint32_t a; asm("{ .reg .u64 t; cvta.to.shared.u64 t, %1; cvt.u32.u64 %0, t; }" : "=r"(a) : "l"(p));
    return a;
}
__device__ __forceinline__ void cpa16(uint32_t dst, const void* src){
    asm volatile("cp.async.cg.shared.global [%0], [%1], 16;\n" :: "r"(dst), "l"(src));
}
__device__ __forceinline__ void cpa8z(uint32_t dst, const void* src, int bytes){
    asm volatile("cp.async.ca.shared.global [%0], [%1], 8, %2;\n" :: "r"(dst), "l"(src), "r"(bytes));
}
__device__ __forceinline__ void cpcommit(){ asm volatile("cp.async.commit_group;\n" ::: "memory"); }
template<int N> __device__ __forceinline__ void cpwait(){ asm volatile("cp.async.wait_group %0;\n" :: "n"(N) : "memory"); }

// ================= prep: W tf32-round + A/D precompute =================
__global__ void k_prep(const float* __restrict__ W_in,
                       const float* __restrict__ A_log_f, const float* __restrict__ A_log_b,
                       const float* __restrict__ D_f, const float* __restrict__ D_b){
    int i = blockIdx.x*256 + threadIdx.x;
    if(i < 1792*64){
        int k = i >> 6;
        g_wt[i] = (k < KTOT) ? tf32r(W_in[i]) : 0.0f;
    }
    if(i < 1024){
        int dir = i >> 9, rem = i & 511;
        const float* Al = dir ? A_log_b : A_log_f;
        g_An[i] = -expf(Al[rem]);
    }
    if(i < 128){
        g_Dc[i] = (i < 64) ? D_f[i] : D_b[i-64];
    }
}

// ================= kernel 0: meta embedding GEMM =================
__global__ void k_meta(const int* __restrict__ site_ids, const int* __restrict__ hours,
                       const float* __restrict__ site_emb, const float* __restrict__ hour_emb,
                       const float* __restrict__ W_meta, const float* __restrict__ b_meta){
    int idx = blockIdx.x*blockDim.x + threadIdx.x;
    int b = idx >> 6, d = idx & 63;
    int s = site_ids[b]; s = min(max(s,0), NSITES-1);
    int hh = hours[b];   hh = min(max(hh,0), 23);
    float acc = b_meta[d];
    #pragma unroll
    for(int j=0;j<8;j++){
        acc += site_emb[s*8+j]*W_meta[j*64+d];
        acc += hour_emb[hh*8+j]*W_meta[(8+j)*64+d];
    }
    g_meta[idx] = acc;
}

// ================= kernel 1: big GEMM (tf32, 2-stage cp.async, 3 CTA/SM) =================
// stage = A[128x36] (4608 fl) + W[32x72] (2304 fl) = 6912 fl; 2 stages = 55296 B
#define K1_STG 6912

__global__ void __launch_bounds__(256,3)
k1(const float* __restrict__ emb, const float* __restrict__ scores,
   const float* __restrict__ b_in,
   const float* __restrict__ lg, const float* __restrict__ lb,
   const float* __restrict__ pos_enc){
    extern __shared__ float sm[];

    const int tid = threadIdx.x, lane = tid & 31, warp = tid >> 5;
    const int gid = lane >> 2, tig = lane & 3;
    const int wm = warp & 3, wn = warp >> 2;
    const long m0 = (long)blockIdx.x * 128;

    const int arow_l = tid & 127;       // A row this thread loads
    const int half   = tid >> 7;        // which 16-col half
    const long arow  = m0 + arow_l;
    const float* embrow = emb + arow*DIN;
    const float* scrow  = scores + arow*DSC;
    const int wrow = tid >> 3, wc8 = (tid & 7)*8;
    const uint32_t smb = s2u(sm);

    float acc[2][4][4];
    #pragma unroll
    for(int i=0;i<2;i++)
        #pragma unroll
        for(int j=0;j<4;j++)
            #pragma unroll
            for(int q=0;q<4;q++) acc[i][j][q]=0.0f;

    auto issue_tile = [&](int ki){
        int st = ki & 1;
        // A tile
        uint32_t ab = smb + (uint32_t)st*K1_STG*4 + arow_l*144 + half*64;
        if(ki < 48){
            const float* src = embrow + ki*32 + half*16;
            cpa16(ab,    src   );
            cpa16(ab+16, src+4 );
            cpa16(ab+32, src+8 );
            cpa16(ab+48, src+12);
        } else {
            int sbase = ki*32 + half*16 - DIN;
            #pragma unroll
            for(int j=0;j<8;j++){
                int s = sbase + j*2;
                int v = DSC - s; v = v<0 ? 0 : (v>2 ? 2 : v);
                cpa8z(ab + j*8, scrow + (v>0 ? s : 0), v*4);
            }
        }
        // W tile
        uint32_t wb = smb + ((uint32_t)st*K1_STG + 4608)*4 + wrow*288 + wc8*4;
        const float* wsrc = g_wt + (ki*32 + wrow)*64 + wc8;
        cpa16(wb,    wsrc  );
        cpa16(wb+16, wsrc+4);
    };

    issue_tile(0); cpcommit();

    for(int ki=0; ki<KTILES; ki++){
        cpwait<0>();
        __syncthreads();                 // tile ki visible; prev buffer reads done

        if(ki+1 < KTILES){ issue_tile(ki+1); cpcommit(); }   // overlaps this tile's MMA

        const float* As = sm + (ki & 1)*K1_STG;          // [128][36]
        const float* Ws = sm + (ki & 1)*K1_STG + 4608;   // [32][72]

        #pragma unroll
        for(int kk=0;kk<32;kk+=8){
            uint32_t af[2][4];
            #pragma unroll
            for(int mt=0;mt<2;mt++){
                int m = wm*32 + mt*16 + gid;
                af[mt][0] = __float_as_uint(As[ m   *36 + kk+tig  ]);
                af[mt][1] = __float_as_uint(As[(m+8)*36 + kk+tig  ]);
                af[mt][2] = __float_as_uint(As[ m   *36 + kk+tig+4]);
                af[mt][3] = __float_as_uint(As[(m+8)*36 + kk+tig+4]);
            }
            #pragma unroll
            for(int nt=0;nt<4;nt++){
                int n = wn*32 + nt*8 + gid;
                uint32_t bf[2];
                bf[0] = __float_as_uint(Ws[(kk+tig  )*72 + n]);
                bf[1] = __float_as_uint(Ws[(kk+tig+4)*72 + n]);
                #pragma unroll
                for(int mt=0;mt<2;mt++) mma8(acc[mt][nt], af[mt], bf);
            }
        }
    }
    __syncthreads();   // all warps done reading last tile before Ht reuse

    // scatter accumulators into smem tile (stride 72)
    float* Ht = sm;
    #pragma unroll
    for(int mt=0;mt<2;mt++)
        #pragma unroll
        for(int nt=0;nt<4;nt++){
            int r = wm*32 + mt*16 + gid;
            int c = wn*32 + nt*8 + 2*tig;
            Ht[ r   *72 + c    ] = acc[mt][nt][0];
            Ht[ r   *72 + c + 1] = acc[mt][nt][1];
            Ht[(r+8)*72 + c    ] = acc[mt][nt][2];
            Ht[(r+8)*72 + c + 1] = acc[mt][nt][3];
        }
    __syncthreads();

    const float bin0 = b_in[lane], bin1 = b_in[lane+32];
    const float gg0 = lg[lane], gg1 = lg[lane+32];
    const float ee0 = lb[lane], ee1 = lb[lane+32];
    #pragma unroll 1
    for(int i=0;i<16;i++){
        int r = warp*16 + i;
        float v0 = Ht[r*72 + lane   ] + bin0;
        float v1 = Ht[r*72 + lane+32] + bin1;
        float mu = warp_sum(v0+v1) * (1.0f/64.0f);
        float d0 = v0-mu, d1 = v1-mu;
        float var = warp_sum(d0*d0 + d1*d1) * (1.0f/64.0f);
        float rs = rsqrtf(var + 1e-5f);
        float y0 = gelu_exact(d0*rs*gg0 + ee0);
        float y1 = gelu_exact(d1*rs*gg1 + ee1);
        long grow = m0 + r;
        int bb = (int)(grow / TT), tt2 = (int)(grow % TT);
        y0 += g_meta[bb*64 + lane   ] + pos_enc[tt2*64 + lane   ];
        y1 += g_meta[bb*64 + lane+32] + pos_enc[tt2*64 + lane+32];
        g_h[grow*64 + lane   ] = y0;
        g_h[grow*64 + lane+32] = y1;
    }
}

// ================= kernel 2: fused proj GEMM + bidirectional scan =================
// CTA = 8 batches = 96 rows, 256 threads.
// smem: hsraw [0,6144) s64 | Hs [6144,12672) s68 | Wps [12672,23424) s168 | bps [23424,23584)
//       prj overlays [6144,22656) s172 after MMA.  total 23584 fl = 94336 B
__global__ void __launch_bounds__(256)
k2f(const float* __restrict__ Wp_f, const float* __restrict__ bp_f,
    const float* __restrict__ Wp_b, const float* __restrict__ bp_b){
    extern __shared__ float sm[];
    float* hsraw = sm;
    float* Hs    = sm + 6144;
    float* Wps   = sm + 12672;
    float* bps   = sm + 23424;
    float* prj   = sm + 6144;     // reuse after MMA

    const int tid = threadIdx.x, lane = tid & 31, warp = tid >> 5;
    const int gid = lane >> 2, tig = lane & 3;
    const long m0 = (long)blockIdx.x * 96;
    const long b0 = (long)blockIdx.x * 8;

    // load h rows: raw for scan + tf32 for MMA
    for(int i=tid; i<96*16; i+=256){
        int r = i >> 4, c4 = (i & 15)*4;
        float4 v = *reinterpret_cast<const float4*>(g_h + (m0+r)*64 + c4);
        *reinterpret_cast<float4*>(hsraw + r*64 + c4) = v;
        float4 w; w.x=tf32r(v.x); w.y=tf32r(v.y); w.z=tf32r(v.z); w.w=tf32r(v.w);
        *reinterpret_cast<float4*>(Hs + r*68 + c4) = w;
    }
    for(int i=tid;i<64*160;i+=256){
        int k = i/160, j = i%160;
        Wps[k*168+j] = tf32r((j<80) ? Wp_f[k*80+j] : Wp_b[k*80+(j-80)]);
    }
    for(int i=tid;i<160;i+=256) bps[i] = (i<80) ? bp_f[i] : bp_b[i-80];
    __syncthreads();

    // proj GEMM: warps 0-5, warp tile 32x80
    float acc[2][10][4];
    if(warp < 6){
        #pragma unroll
        for(int a=0;a<2;a++)
            #pragma unroll
            for(int b=0;b<10;b++)
                #pragma unroll
                for(int q=0;q<4;q++) acc[a][b][q]=0.0f;
        const int wm = warp % 3, wn = warp / 3;
        #pragma unroll
        for(int kk=0;kk<64;kk+=8){
            uint32_t af[2][4];
            #pragma unroll
            for(int mt=0;mt<2;mt++){
                int m = wm*32 + mt*16 + gid;
                af[mt][0] = __float_as_uint(Hs[ m   *68 + kk+tig  ]);
                af[mt][1] = __float_as_uint(Hs[(m+8)*68 + kk+tig  ]);
                af[mt][2] = __float_as_uint(Hs[ m   *68 + kk+tig+4]);
                af[mt][3] = __float_as_uint(Hs[(m+8)*68 + kk+tig+4]);
            }
            #pragma unroll
            for(int nt=0;nt<10;nt++){
                int n = wn*80 + nt*8 + gid;
                uint32_t bf[2];
                bf[0] = __float_as_uint(Wps[(kk+tig  )*168 + n]);
                bf[1] = __float_as_uint(Wps[(kk+tig+4)*168 + n]);
                #pragma unroll
                for(int mt=0;mt<2;mt++) mma8(acc[mt][nt], af[mt], bf);
            }
        }
    }
    __syncthreads();   // Hs/Wps reads complete before prj overwrite

    if(warp < 6){
        const int wm = warp % 3, wn = warp / 3;
        #pragma unroll
        for(int mt=0;mt<2;mt++)
            #pragma unroll
            for(int nt=0;nt<10;nt++){
                int r = wm*32 + mt*16 + gid;
                int c = wn*80 + nt*8 + 2*tig;
                float b0v = bps[c], b1v = bps[c+1];
                prj[ r   *172 + c    ] = acc[mt][nt][0] + b0v;
                prj[ r   *172 + c + 1] = acc[mt][nt][1] + b1v;
                prj[(r+8)*172 + c    ] = acc[mt][nt][2] + b0v;
                prj[(r+8)*172 + c + 1] = acc[mt][nt][3] + b1v;
            }
    }
    __syncthreads();

    // scan: 1024 units (8 batches x 2 dirs x 64 ch), 4 per thread
    #pragma unroll 1
    for(int q=0;q<4;q++){
        int u = tid + 256*q;
        int lb = u >> 7, dir = (u >> 6) & 1, d = u & 63;
        float Arow[DSS];
        #pragma unroll
        for(int n=0;n<DSS;n++) Arow[n] = g_An[dir*512 + d*8 + n];
        const float Dd = g_Dc[dir*64 + d];
        float h[DSS];
        #pragma unroll
        for(int n=0;n<DSS;n++) h[n]=0.0f;
        const float* pb = prj + lb*12*172;
        const float* xb = hsraw + lb*12*64;
        float* yout = g_y + (b0+lb)*TT*128 + dir*64 + d;
        const int joff = dir ? 80 : 0;

        for(int s=0;s<TT;s++){
            int t = dir ? (TT-1-s) : s;
            const float* p = pb + t*172 + joff;
            float pd = p[d];
            float delta = (pd > 15.0f) ? pd : __logf(1.0f + __expf(pd));
            float x = xb[t*64 + d];
            float dx = delta * x;
            float y = 0.0f;
            #pragma unroll
            for(int n=0;n<DSS;n++){
                float dA = __expf(delta * Arow[n]);
                h[n] = dA*h[n] + dx*p[64+n];
                y = fmaf(h[n], p[72+n], y);
            }
            yout[t*128] = y + x*Dd;
        }
    }
}

// ================= kernel 3: merge GEMM + LN + out GEMM (512 threads) =================
__global__ void __launch_bounds__(512)
k3(const float* __restrict__ W_merge, const float* __restrict__ b_merge,
   const float* __restrict__ lgm, const float* __restrict__ lbm,
   const float* __restrict__ W_out, const float* __restrict__ b_out,
   float* __restrict__ out){
    extern __shared__ float sm[];
    float* Ys  = sm;
    float* Wsm = sm + 16896;
    float* Wos = sm + 26112;
    float* Ah  = sm + 43008;
    float* bm  = sm + 51712;
    float* lgs = sm + 51776;
    float* lbs = sm + 51840;
    float* bo  = sm + 51904;

    const int tid = threadIdx.x, lane = tid & 31, warp = tid >> 5;
    const int gid = lane >> 2, tig = lane & 3;
    const long m0 = (long)blockIdx.x * 128;

    {   // Y tile [128x128] stride 132
        int n4 = tid & 31, r0 = tid >> 5;
        #pragma unroll
        for(int r=r0; r<128; r+=16){
            float4 v = *reinterpret_cast<const float4*>(g_y + (m0+r)*128 + n4*4);
            float4 w; w.x=tf32r(v.x); w.y=tf32r(v.y); w.z=tf32r(v.z); w.w=tf32r(v.w);
            *reinterpret_cast<float4*>(Ys + r*132 + n4*4) = w;
        }
    }
    {   // W_merge [128x64] stride 72
        int n4 = tid & 15, r0 = tid >> 4;
        #pragma unroll
        for(int r=r0; r<128; r+=32){
            float4 v = *reinterpret_cast<const float4*>(W_merge + r*64 + n4*4);
            float4 w; w.x=tf32r(v.x); w.y=tf32r(v.y); w.z=tf32r(v.z); w.w=tf32r(v.w);
            *reinterpret_cast<float4*>(Wsm + r*72 + n4*4) = w;
        }
    }
    for(int i=tid;i<64*264;i+=512) Wos[i] = 0.0f;
    __syncthreads();
    for(int i=tid;i<64*NC;i+=512) Wos[(i/NC)*264 + (i%NC)] = tf32r(W_out[i]);
    if(tid<64){ bm[tid]=b_merge[tid]; lgs[tid]=lgm[tid]; lbs[tid]=lbm[tid]; }
    for(int i=tid;i<NC;i+=512) bo[i] = b_out[i];
    __syncthreads();

    // ---- phase A: C1[128x64] = Y @ Wm ----
    {
        const int wm = warp & 3, wn = warp >> 2;
        float acc[2][2][4];
        #pragma unroll
        for(int a=0;a<2;a++)
            #pragma unroll
            for(int b=0;b<2;b++)
                #pragma unroll
                for(int q=0;q<4;q++) acc[a][b][q]=0.0f;

        #pragma unroll
        for(int kk=0;kk<128;kk+=8){
            uint32_t af[2][4];
            #pragma unroll
            for(int mt=0;mt<2;mt++){
                int m = wm*32 + mt*16 + gid;
                af[mt][0] = __float_as_uint(Ys[ m   *132 + kk+tig  ]);
                af[mt][1] = __float_as_uint(Ys[(m+8)*132 + kk+tig  ]);
                af[mt][2] = __float_as_uint(Ys[ m   *132 + kk+tig+4]);
                af[mt][3] = __float_as_uint(Ys[(m+8)*132 + kk+tig+4]);
            }
            #pragma unroll
            for(int nt=0;nt<2;nt++){
                int n = wn*16 + nt*8 + gid;
                uint32_t bf[2];
                bf[0] = __float_as_uint(Wsm[(kk+tig  )*72 + n]);
                bf[1] = __float_as_uint(Wsm[(kk+tig+4)*72 + n]);
                #pragma unroll
                for(int mt=0;mt<2;mt++) mma8(acc[mt][nt], af[mt], bf);
            }
        }
        __syncthreads();

        float* Ht = sm;
        #pragma unroll
        for(int mt=0;mt<2;mt++)
            #pragma unroll
            for(int nt=0;nt<2;nt++){
                int r = wm*32 + mt*16 + gid;
                int c = wn*16 + nt*8 + 2*tig;
                Ht[ r   *72 + c    ] = acc[mt][nt][0];
                Ht[ r   *72 + c + 1] = acc[mt][nt][1];
                Ht[(r+8)*72 + c    ] = acc[mt][nt][2];
                Ht[(r+8)*72 + c + 1] = acc[mt][nt][3];
            }
        __syncthreads();
    }

    // ---- LN: Ah = tf32(LN(C1 + bm + residual)) ----
    {
        float* Ht = sm;
        const float b0 = bm[lane], b1 = bm[lane+32];
        const float gg0 = lgs[lane], gg1 = lgs[lane+32];
        const float ee0 = lbs[lane], ee1 = lbs[lane+32];
        #pragma unroll 1
        for(int i=0;i<8;i++){
            int r = warp*8 + i;
            long gr = m0 + r;
            float v0 = Ht[r*72 + lane   ] + b0 + g_h[gr*64 + lane   ];
            float v1 = Ht[r*72 + lane+32] + b1 + g_h[gr*64 + lane+32];
            float mu = warp_sum(v0+v1) * (1.0f/64.0f);
            float d0 = v0-mu, d1 = v1-mu;
            float var = warp_sum(d0*d0 + d1*d1) * (1.0f/64.0f);
            float rs = rsqrtf(var + 1e-5f);
            Ah[r*68 + lane   ] = tf32r(d0*rs*gg0 + ee0);
            Ah[r*68 + lane+32] = tf32r(d1*rs*gg1 + ee1);
        }
        __syncthreads();
    }

    // ---- phase B: out = Ah @ Wo ----
    {
        const int wm2 = warp & 1, wn2 = warp >> 1;
        float acc2[4][4][4];
        #pragma unroll
        for(int a=0;a<4;a++)
            #pragma unroll
            for(int b=0;b<4;b++)
                #pragma unroll
                for(int q=0;q<4;q++) acc2[a][b][q]=0.0f;

        #pragma unroll
        for(int kk=0;kk<64;kk+=8){
            uint32_t af[4][4];
            #pragma unroll
            for(int mt=0;mt<4;mt++){
                int m = wm2*64 + mt*16 + gid;
                af[mt][0] = __float_as_uint(Ah[ m   *68 + kk+tig  ]);
                af[mt][1] = __float_as_uint(Ah[(m+8)*68 + kk+tig  ]);
                af[mt][2] = __float_as_uint(Ah[ m   *68 + kk+tig+4]);
                af[mt][3] = __float_as_uint(Ah[(m+8)*68 + kk+tig+4]);
            }
            #pragma unroll
            for(int nt=0;nt<4;nt++){
                int n = wn2*32 + nt*8 + gid;
                uint32_t bf[2];
                bf[0] = __float_as_uint(Wos[(kk+tig  )*264 + n]);
                bf[1] = __float_as_uint(Wos[(kk+tig+4)*264 + n]);
                #pragma unroll
                for(int mt=0;mt<4;mt++) mma8(acc2[mt][nt], af[mt], bf);
            }
        }
        __syncthreads();

        float* Pg = sm;    // stride 264
        #pragma unroll
        for(int mt=0;mt<4;mt++)
            #pragma unroll
            for(int nt=0;nt<4;nt++){
                int r = wm2*64 + mt*16 + gid;
                int c = wn2*32 + nt*8 + 2*tig;
                if(c < NC){
                    float b0 = bo[c], b1 = (c+1<NC) ? bo[c+1] : 0.0f;
                    Pg[ r   *264 + c    ] = acc2[mt][nt][0] + b0;
                    Pg[ r   *264 + c + 1] = acc2[mt][nt][1] + b1;
                    Pg[(r+8)*264 + c    ] = acc2[mt][nt][2] + b0;
                    Pg[(r+8)*264 + c + 1] = acc2[mt][nt][3] + b1;
                }
            }
        __syncthreads();

        #pragma unroll 1
        for(int i=0;i<8;i++){
            int r = warp*8 + i;
            long gr = m0 + r;
            #pragma unroll
            for(int q=0;q<8;q++){
                int j = lane + 32*q;
                if(j < NC) out[gr*NC + j] = Pg[r*264 + j];
            }
        }
    }
}

// ================= launch =================
extern "C" void kernel_launch(void* const* d_in, const int* in_sizes, int n_in,
                              void* d_out, int out_size){
    const float* emb      = (const float*)d_in[0];
    const float* scores   = (const float*)d_in[1];
    const int*   site_ids = (const int*)  d_in[2];
    const int*   hours    = (const int*)  d_in[3];
    const float* W_in     = (const float*)d_in[4];
    const float* b_in     = (const float*)d_in[5];
    const float* ln_in_g  = (const float*)d_in[6];
    const float* ln_in_b  = (const float*)d_in[7];
    const float* site_emb = (const float*)d_in[8];
    const float* hour_emb = (const float*)d_in[9];
    const float* W_meta   = (const float*)d_in[10];
    const float* b_meta   = (const float*)d_in[11];
    const float* pos_enc  = (const float*)d_in[12];
    const float* A_log_f  = (const float*)d_in[13];
    const float* Wp_f     = (const float*)d_in[14];
    const float* bp_f     = (const float*)d_in[15];
    const float* D_f      = (const float*)d_in[16];
    const float* A_log_b  = (const float*)d_in[17];
    const float* Wp_b     = (const float*)d_in[18];
    const float* bp_b     = (const float*)d_in[19];
    const float* D_b      = (const float*)d_in[20];
    const float* W_merge  = (const float*)d_in[21];
    const float* b_merge  = (const float*)d_in[22];
    const float* ln_g     = (const float*)d_in[23];
    const float* ln_b     = (const float*)d_in[24];
    const float* W_out    = (const float*)d_in[25];
    const float* b_out    = (const float*)d_in[26];
    float* out = (float*)d_out;

    cudaFuncSetAttribute(k1,  cudaFuncAttributeMaxDynamicSharedMemorySize, 55296);
    cudaFuncSetAttribute(k2f, cudaFuncAttributeMaxDynamicSharedMemorySize, 94336);
    cudaFuncSetAttribute(k3,  cudaFuncAttributeMaxDynamicSharedMemorySize, 208576);

    k_prep<<<448, 256>>>(W_in, A_log_f, A_log_b, D_f, D_b);
    k_meta<<<(BATCH*DM)/256, 256>>>(site_ids, hours, site_emb, hour_emb, W_meta, b_meta);
    k1<<<NROWS/128, 256, 55296>>>(emb, scores, b_in, ln_in_g, ln_in_b, pos_enc);
    k2f<<<NROWS/96, 256, 94336>>>(Wp_f, bp_f, Wp_b, bp_b);
    k3<<<NROWS/128, 512, 208576>>>(W_merge, b_merge, ln_g, ln_b, W_out, b_out, out);
}